// round 1
// baseline (speedup 1.0000x reference)
#include <cuda_runtime.h>
#include <math.h>

// Problem constants
#define BB 2
#define TT 2048
#define HH 16
#define ND 512          // head dim
#define HN (HH*ND)      // 8192

// Tiling
#define BM 64           // query rows per CTA
#define BN 64           // key cols per tile
#define KD 64           // d-chunk for K streaming
#define DV 128          // d-chunk for V streaming
#define NTHREADS 512    // 16 warps; warp w owns query rows 4w..4w+3
#define KS_STRIDE 66    // padded stride for transposed K chunk (conflict-free float2 reads)
#define PS_STRIDE 64

#define TWO_PI_F 6.2831853071795864769f

// Scratch for roped Q/K in [b,h,t,d] layout (device globals: allocation-free rule)
__device__ float g_Qr[(size_t)BB*HH*TT*ND];
__device__ float g_Kr[(size_t)BB*HH*TT*ND];

// float4 component by (unrolled) constant index
#define F4C(v,k) ((k)==0?(v).x:((k)==1?(v).y:((k)==2?(v).z:(v).w)))

// ---------------------------------------------------------------------------
// RoPE pre-pass: one block per (b,t,h) row, one thread per even/odd pair.
// Replicates reference arithmetic: freq = 1/theta^(q/D)/2pi; ang = frac(t*freq)*2pi
// ---------------------------------------------------------------------------
__global__ void rope_kernel(const float* __restrict__ Q, const float* __restrict__ K) {
    int pair = threadIdx.x;              // 0..255
    int row  = blockIdx.x;               // (b*T + t)*H + h
    int h  = row & (HH - 1);
    int bt = row >> 4;                   // b*T + t
    int t  = bt & (TT - 1);
    int b  = bt >> 11;

    float qf   = 2.0f * (float)pair;     // floor(d/2)*2, shared by the pair
    float freq = 1.0f / powf(10000.0f, qf * (1.0f/(float)ND)) * (1.0f/TWO_PI_F);
    float phase = (float)t * freq;
    float ang = (phase - floorf(phase)) * TWO_PI_F;
    float sv, cv;
    sincosf(ang, &sv, &cv);

    size_t in_idx  = (size_t)row * ND + 2*pair;
    size_t out_idx = (((size_t)(b*HH + h))*TT + (size_t)t)*ND + 2*pair;

    float2 qv = *(const float2*)(Q + in_idx);
    float2 kv = *(const float2*)(K + in_idx);
    float2 qo, ko;
    qo.x = qv.x*cv - qv.y*sv;  qo.y = qv.y*cv + qv.x*sv;
    ko.x = kv.x*cv - kv.y*sv;  ko.y = kv.y*cv + kv.x*sv;
    *(float2*)(g_Qr + out_idx) = qo;
    *(float2*)(g_Kr + out_idx) = ko;
}

// ---------------------------------------------------------------------------
// Flash attention (fp32). CTA = (qtile, h, b). 512 threads.
// Warp w owns query rows 4w..4w+3; lane owns S cols {2*lane,2*lane+1},
// O cols {lane + 32c : c=0..15}. Row softmax = warp shfl butterflies.
// ---------------------------------------------------------------------------
__global__ void __launch_bounds__(NTHREADS, 1)
attn_kernel(const float* __restrict__ V, float* __restrict__ out) {
    extern __shared__ float smem[];
    float* Qs = smem;                        // BM*ND      = 32768 floats
    float* Ks = Qs + BM*ND;                  // KD*66      =  4224 (transposed chunk)
    float* Vs = Ks + KD*KS_STRIDE;           // BN*DV      =  8192
    float* Ps = Vs + BN*DV;                  // BM*64      =  4096

    const int tid  = threadIdx.x;
    const int warp = tid >> 5;
    const int lane = tid & 31;

    // launch long (diagonal-heavy) blocks first for better tail balance
    const int qt = (int)(gridDim.x - 1u - blockIdx.x);
    const int h  = blockIdx.y;
    const int b  = blockIdx.z;
    const int q0 = qt * BM;

    const float* Qr = g_Qr + ((size_t)(b*HH + h))*TT*ND;
    const float* Kr = g_Kr + ((size_t)(b*HH + h))*TT*ND;
    const float* Vg = V + (size_t)b*TT*HN + (size_t)h*ND;

    // Q tile is contiguous in g_Qr: straight float4 copy
    {
        const float4* src = (const float4*)(Qr + (size_t)q0*ND);
        float4* dst = (float4*)Qs;
        #pragma unroll
        for (int r = 0; r < (BM*ND/4)/NTHREADS; r++) {   // 16 iters
            int f = tid + NTHREADS*r;
            dst[f] = src[f];
        }
    }

    float o[4][16];
    float m[4], l[4];
    #pragma unroll
    for (int i = 0; i < 4; i++) {
        m[i] = -1e30f; l[i] = 0.0f;
        #pragma unroll
        for (int c = 0; c < 16; c++) o[i][c] = 0.0f;
    }

    const float scale = 0.044194173824159220f;  // 1/sqrt(512)
    const int ntiles = qt + 1;

    for (int jt = 0; jt < ntiles; jt++) {
        const int j0 = jt * BN;
        float s[4][2];
        #pragma unroll
        for (int i = 0; i < 4; i++) { s[i][0] = 0.0f; s[i][1] = 0.0f; }

        // ---- S = Q K^T over d-chunks of KD ----
        #pragma unroll 1
        for (int dc = 0; dc < ND/KD; dc++) {
            // prefetch chunk (64 keys x 64 d) into regs: 2 float4/thread
            float4 kbuf[2];
            #pragma unroll
            for (int r = 0; r < 2; r++) {
                int f = tid + NTHREADS*r;
                int krow = f >> 4, kseg = f & 15;
                kbuf[r] = *(const float4*)(Kr + (size_t)(j0 + krow)*ND + dc*KD + kseg*4);
            }
            __syncthreads();   // WAR on Ks
            #pragma unroll
            for (int r = 0; r < 2; r++) {
                int f = tid + NTHREADS*r;
                int krow = f >> 4, kseg = f & 15;
                float* p = Ks + (kseg*4)*KS_STRIDE + krow;   // transposed [d][key]
                p[0*KS_STRIDE] = kbuf[r].x;
                p[1*KS_STRIDE] = kbuf[r].y;
                p[2*KS_STRIDE] = kbuf[r].z;
                p[3*KS_STRIDE] = kbuf[r].w;
            }
            __syncthreads();

            const float* qbase = Qs + (4*warp)*ND + dc*KD;
            #pragma unroll
            for (int kk4 = 0; kk4 < KD/4; kk4++) {
                float4 qv0 = *(const float4*)(qbase + 0*ND + kk4*4);  // broadcast LDS
                float4 qv1 = *(const float4*)(qbase + 1*ND + kk4*4);
                float4 qv2 = *(const float4*)(qbase + 2*ND + kk4*4);
                float4 qv3 = *(const float4*)(qbase + 3*ND + kk4*4);
                #pragma unroll
                for (int kk = 0; kk < 4; kk++) {
                    float2 kv = *(const float2*)(Ks + (kk4*4 + kk)*KS_STRIDE + 2*lane);
                    s[0][0] += F4C(qv0,kk)*kv.x;  s[0][1] += F4C(qv0,kk)*kv.y;
                    s[1][0] += F4C(qv1,kk)*kv.x;  s[1][1] += F4C(qv1,kk)*kv.y;
                    s[2][0] += F4C(qv2,kk)*kv.x;  s[2][1] += F4C(qv2,kk)*kv.y;
                    s[3][0] += F4C(qv3,kk)*kv.x;  s[3][1] += F4C(qv3,kk)*kv.y;
                }
            }
        }

        // ---- online softmax (warp-local: all 64 cols of a row live in this warp) ----
        #pragma unroll
        for (int i = 0; i < 4; i++) {
            float s0 = s[i][0]*scale, s1 = s[i][1]*scale;
            if (jt == ntiles - 1) {            // diagonal tile: mask col > row
                int r = 4*warp + i;
                if (2*lane     > r) s0 = -1e30f;
                if (2*lane + 1 > r) s1 = -1e30f;
            }
            float mx = fmaxf(s0, s1);
            #pragma unroll
            for (int off = 16; off > 0; off >>= 1)
                mx = fmaxf(mx, __shfl_xor_sync(0xffffffffu, mx, off));
            float mn = fmaxf(m[i], mx);
            float p0 = __expf(s0 - mn);
            float p1 = __expf(s1 - mn);
            float ps = p0 + p1;
            #pragma unroll
            for (int off = 16; off > 0; off >>= 1)
                ps += __shfl_xor_sync(0xffffffffu, ps, off);
            float alpha = __expf(m[i] - mn);
            l[i] = l[i]*alpha + ps;
            m[i] = mn;
            #pragma unroll
            for (int c = 0; c < 16; c++) o[i][c] *= alpha;
            *(float2*)(Ps + (4*warp + i)*PS_STRIDE + 2*lane) = make_float2(p0, p1);
        }
        __syncwarp();

        // ---- O += P V over d-chunks of DV ----
        #pragma unroll
        for (int vc = 0; vc < ND/DV; vc++) {
            float4 vbuf[4];
            #pragma unroll
            for (int r = 0; r < 4; r++) {
                int f = tid + NTHREADS*r;
                int vrow = f >> 5, vseg = f & 31;
                vbuf[r] = *(const float4*)(Vg + (size_t)(j0 + vrow)*HN + vc*DV + vseg*4);
            }
            __syncthreads();   // WAR on Vs
            #pragma unroll
            for (int r = 0; r < 4; r++) {
                int f = tid + NTHREADS*r;
                int vrow = f >> 5, vseg = f & 31;
                *(float4*)(Vs + vrow*DV + vseg*4) = vbuf[r];
            }
            __syncthreads();

            const float* prow = Ps + 4*warp*PS_STRIDE;
            #pragma unroll 4
            for (int j = 0; j < BN; j++) {
                float p0 = prow[0*PS_STRIDE + j];   // broadcast LDS
                float p1 = prow[1*PS_STRIDE + j];
                float p2 = prow[2*PS_STRIDE + j];
                float p3 = prow[3*PS_STRIDE + j];
                const float* vr = Vs + j*DV + lane;
                #pragma unroll
                for (int c = 0; c < 4; c++) {
                    float vv = vr[32*c];            // conflict-free
                    o[0][vc*4 + c] += p0*vv;
                    o[1][vc*4 + c] += p1*vv;
                    o[2][vc*4 + c] += p2*vv;
                    o[3][vc*4 + c] += p3*vv;
                }
            }
        }
    }

    // ---- epilogue: normalize and store to (b,t,h,d) layout ----
    #pragma unroll
    for (int i = 0; i < 4; i++) {
        float inv = 1.0f / l[i];
        int t = q0 + 4*warp + i;
        float* op = out + ((size_t)(b*TT + t))*HN + (size_t)h*ND + lane;
        #pragma unroll
        for (int c = 0; c < 16; c++) op[32*c] = o[i][c] * inv;
    }
}

// ---------------------------------------------------------------------------
extern "C" void kernel_launch(void* const* d_in, const int* in_sizes, int n_in,
                              void* d_out, int out_size) {
    (void)in_sizes; (void)n_in; (void)out_size;
    const float* Q = (const float*)d_in[0];
    const float* K = (const float*)d_in[1];
    const float* V = (const float*)d_in[2];
    float* out = (float*)d_out;

    rope_kernel<<<BB*TT*HH, 256>>>(Q, K);

    size_t smem_bytes = (size_t)(BM*ND + KD*KS_STRIDE + BN*DV + BM*PS_STRIDE) * sizeof(float);
    cudaFuncSetAttribute(attn_kernel, cudaFuncAttributeMaxDynamicSharedMemorySize, (int)smem_bytes);
    dim3 grid(TT/BM, HH, BB);
    attn_kernel<<<grid, NTHREADS, smem_bytes>>>(V, out);
}

// round 2
// speedup vs baseline: 1.0006x; 1.0006x over previous
#include <cuda_runtime.h>
#include <math.h>

// Problem constants
#define BB 2
#define TT 2048
#define HH 16
#define ND 512          // head dim
#define HN (HH*ND)      // 8192

// Tiling
#define BM 64           // query rows per CTA
#define BN 64           // key cols per tile
#define KD 64           // d-chunk for K streaming
#define DV 128          // d-chunk for V streaming
#define NTHREADS 512    // 16 warps; warp w owns query rows 4w..4w+3
#define KS_STRIDE 66    // padded stride for transposed K chunk (conflict-free float2 reads)
#define PS_STRIDE 64

#define TWO_PI_F 6.2831853071795864769f

// Scratch for roped Q/K in [b,h,t,d] layout (device globals: allocation-free rule)
__device__ float g_Qr[(size_t)BB*HH*TT*ND];
__device__ float g_Kr[(size_t)BB*HH*TT*ND];

// float4 component by (unrolled) constant index
#define F4C(v,k) ((k)==0?(v).x:((k)==1?(v).y:((k)==2?(v).z:(v).w)))

// ---------------------------------------------------------------------------
// RoPE pre-pass: one block per (b,t,h) row, one thread per even/odd pair.
// Replicates reference arithmetic: freq = 1/theta^(q/D)/2pi; ang = frac(t*freq)*2pi
// ---------------------------------------------------------------------------
__global__ void rope_kernel(const float* __restrict__ Q, const float* __restrict__ K) {
    int pair = threadIdx.x;              // 0..255
    int row  = blockIdx.x;               // (b*T + t)*H + h
    int h  = row & (HH - 1);
    int bt = row >> 4;                   // b*T + t
    int t  = bt & (TT - 1);
    int b  = bt >> 11;

    float qf   = 2.0f * (float)pair;     // floor(d/2)*2, shared by the pair
    float freq = 1.0f / powf(10000.0f, qf * (1.0f/(float)ND)) * (1.0f/TWO_PI_F);
    float phase = (float)t * freq;
    float ang = (phase - floorf(phase)) * TWO_PI_F;
    float sv, cv;
    sincosf(ang, &sv, &cv);

    size_t in_idx  = (size_t)row * ND + 2*pair;
    size_t out_idx = (((size_t)(b*HH + h))*TT + (size_t)t)*ND + 2*pair;

    float2 qv = *(const float2*)(Q + in_idx);
    float2 kv = *(const float2*)(K + in_idx);
    float2 qo, ko;
    qo.x = qv.x*cv - qv.y*sv;  qo.y = qv.y*cv + qv.x*sv;
    ko.x = kv.x*cv - kv.y*sv;  ko.y = kv.y*cv + kv.x*sv;
    *(float2*)(g_Qr + out_idx) = qo;
    *(float2*)(g_Kr + out_idx) = ko;
}

// ---------------------------------------------------------------------------
// Flash attention (fp32). CTA = (qtile, h, b). 512 threads.
// Warp w owns query rows 4w..4w+3; lane owns S cols {2*lane,2*lane+1},
// O cols {lane + 32c : c=0..15}. Row softmax = warp shfl butterflies.
// ---------------------------------------------------------------------------
__global__ void __launch_bounds__(NTHREADS, 1)
attn_kernel(const float* __restrict__ V, float* __restrict__ out) {
    extern __shared__ float smem[];
    float* Qs = smem;                        // BM*ND      = 32768 floats
    float* Ks = Qs + BM*ND;                  // KD*66      =  4224 (transposed chunk)
    float* Vs = Ks + KD*KS_STRIDE;           // BN*DV      =  8192
    float* Ps = Vs + BN*DV;                  // BM*64      =  4096

    const int tid  = threadIdx.x;
    const int warp = tid >> 5;
    const int lane = tid & 31;

    // launch long (diagonal-heavy) blocks first for better tail balance
    const int qt = (int)(gridDim.x - 1u - blockIdx.x);
    const int h  = blockIdx.y;
    const int b  = blockIdx.z;
    const int q0 = qt * BM;

    const float* Qr = g_Qr + ((size_t)(b*HH + h))*TT*ND;
    const float* Kr = g_Kr + ((size_t)(b*HH + h))*TT*ND;
    const float* Vg = V + (size_t)b*TT*HN + (size_t)h*ND;

    // Q tile is contiguous in g_Qr: straight float4 copy
    {
        const float4* src = (const float4*)(Qr + (size_t)q0*ND);
        float4* dst = (float4*)Qs;
        #pragma unroll
        for (int r = 0; r < (BM*ND/4)/NTHREADS; r++) {   // 16 iters
            int f = tid + NTHREADS*r;
            dst[f] = src[f];
        }
    }

    float o[4][16];
    float m[4], l[4];
    #pragma unroll
    for (int i = 0; i < 4; i++) {
        m[i] = -1e30f; l[i] = 0.0f;
        #pragma unroll
        for (int c = 0; c < 16; c++) o[i][c] = 0.0f;
    }

    const float scale = 0.044194173824159220f;  // 1/sqrt(512)
    const int ntiles = qt + 1;

    for (int jt = 0; jt < ntiles; jt++) {
        const int j0 = jt * BN;
        float s[4][2];
        #pragma unroll
        for (int i = 0; i < 4; i++) { s[i][0] = 0.0f; s[i][1] = 0.0f; }

        // ---- S = Q K^T over d-chunks of KD ----
        #pragma unroll 1
        for (int dc = 0; dc < ND/KD; dc++) {
            // prefetch chunk (64 keys x 64 d) into regs: 2 float4/thread
            float4 kbuf[2];
            #pragma unroll
            for (int r = 0; r < 2; r++) {
                int f = tid + NTHREADS*r;
                int krow = f >> 4, kseg = f & 15;
                kbuf[r] = *(const float4*)(Kr + (size_t)(j0 + krow)*ND + dc*KD + kseg*4);
            }
            __syncthreads();   // WAR on Ks
            #pragma unroll
            for (int r = 0; r < 2; r++) {
                int f = tid + NTHREADS*r;
                int krow = f >> 4, kseg = f & 15;
                float* p = Ks + (kseg*4)*KS_STRIDE + krow;   // transposed [d][key]
                p[0*KS_STRIDE] = kbuf[r].x;
                p[1*KS_STRIDE] = kbuf[r].y;
                p[2*KS_STRIDE] = kbuf[r].z;
                p[3*KS_STRIDE] = kbuf[r].w;
            }
            __syncthreads();

            const float* qbase = Qs + (4*warp)*ND + dc*KD;
            #pragma unroll
            for (int kk4 = 0; kk4 < KD/4; kk4++) {
                float4 qv0 = *(const float4*)(qbase + 0*ND + kk4*4);  // broadcast LDS
                float4 qv1 = *(const float4*)(qbase + 1*ND + kk4*4);
                float4 qv2 = *(const float4*)(qbase + 2*ND + kk4*4);
                float4 qv3 = *(const float4*)(qbase + 3*ND + kk4*4);
                #pragma unroll
                for (int kk = 0; kk < 4; kk++) {
                    float2 kv = *(const float2*)(Ks + (kk4*4 + kk)*KS_STRIDE + 2*lane);
                    s[0][0] += F4C(qv0,kk)*kv.x;  s[0][1] += F4C(qv0,kk)*kv.y;
                    s[1][0] += F4C(qv1,kk)*kv.x;  s[1][1] += F4C(qv1,kk)*kv.y;
                    s[2][0] += F4C(qv2,kk)*kv.x;  s[2][1] += F4C(qv2,kk)*kv.y;
                    s[3][0] += F4C(qv3,kk)*kv.x;  s[3][1] += F4C(qv3,kk)*kv.y;
                }
            }
        }

        // ---- online softmax (warp-local: all 64 cols of a row live in this warp) ----
        #pragma unroll
        for (int i = 0; i < 4; i++) {
            float s0 = s[i][0]*scale, s1 = s[i][1]*scale;
            if (jt == ntiles - 1) {            // diagonal tile: mask col > row
                int r = 4*warp + i;
                if (2*lane     > r) s0 = -1e30f;
                if (2*lane + 1 > r) s1 = -1e30f;
            }
            float mx = fmaxf(s0, s1);
            #pragma unroll
            for (int off = 16; off > 0; off >>= 1)
                mx = fmaxf(mx, __shfl_xor_sync(0xffffffffu, mx, off));
            float mn = fmaxf(m[i], mx);
            float p0 = __expf(s0 - mn);
            float p1 = __expf(s1 - mn);
            float ps = p0 + p1;
            #pragma unroll
            for (int off = 16; off > 0; off >>= 1)
                ps += __shfl_xor_sync(0xffffffffu, ps, off);
            float alpha = __expf(m[i] - mn);
            l[i] = l[i]*alpha + ps;
            m[i] = mn;
            #pragma unroll
            for (int c = 0; c < 16; c++) o[i][c] *= alpha;
            *(float2*)(Ps + (4*warp + i)*PS_STRIDE + 2*lane) = make_float2(p0, p1);
        }
        __syncwarp();

        // ---- O += P V over d-chunks of DV ----
        #pragma unroll
        for (int vc = 0; vc < ND/DV; vc++) {
            float4 vbuf[4];
            #pragma unroll
            for (int r = 0; r < 4; r++) {
                int f = tid + NTHREADS*r;
                int vrow = f >> 5, vseg = f & 31;
                vbuf[r] = *(const float4*)(Vg + (size_t)(j0 + vrow)*HN + vc*DV + vseg*4);
            }
            __syncthreads();   // WAR on Vs
            #pragma unroll
            for (int r = 0; r < 4; r++) {
                int f = tid + NTHREADS*r;
                int vrow = f >> 5, vseg = f & 31;
                *(float4*)(Vs + vrow*DV + vseg*4) = vbuf[r];
            }
            __syncthreads();

            const float* prow = Ps + 4*warp*PS_STRIDE;
            #pragma unroll 4
            for (int j = 0; j < BN; j++) {
                float p0 = prow[0*PS_STRIDE + j];   // broadcast LDS
                float p1 = prow[1*PS_STRIDE + j];
                float p2 = prow[2*PS_STRIDE + j];
                float p3 = prow[3*PS_STRIDE + j];
                const float* vr = Vs + j*DV + lane;
                #pragma unroll
                for (int c = 0; c < 4; c++) {
                    float vv = vr[32*c];            // conflict-free
                    o[0][vc*4 + c] += p0*vv;
                    o[1][vc*4 + c] += p1*vv;
                    o[2][vc*4 + c] += p2*vv;
                    o[3][vc*4 + c] += p3*vv;
                }
            }
        }
    }

    // ---- epilogue: normalize and store to (b,t,h,d) layout ----
    #pragma unroll
    for (int i = 0; i < 4; i++) {
        float inv = 1.0f / l[i];
        int t = q0 + 4*warp + i;
        float* op = out + ((size_t)(b*TT + t))*HN + (size_t)h*ND + lane;
        #pragma unroll
        for (int c = 0; c < 16; c++) op[32*c] = o[i][c] * inv;
    }
}

// ---------------------------------------------------------------------------
extern "C" void kernel_launch(void* const* d_in, const int* in_sizes, int n_in,
                              void* d_out, int out_size) {
    (void)in_sizes; (void)n_in; (void)out_size;
    const float* Q = (const float*)d_in[0];
    const float* K = (const float*)d_in[1];
    const float* V = (const float*)d_in[2];
    float* out = (float*)d_out;

    rope_kernel<<<BB*TT*HH, 256>>>(Q, K);

    size_t smem_bytes = (size_t)(BM*ND + KD*KS_STRIDE + BN*DV + BM*PS_STRIDE) * sizeof(float);
    cudaFuncSetAttribute(attn_kernel, cudaFuncAttributeMaxDynamicSharedMemorySize, (int)smem_bytes);
    dim3 grid(TT/BM, HH, BB);
    attn_kernel<<<grid, NTHREADS, smem_bytes>>>(V, out);
}